// round 4
// baseline (speedup 1.0000x reference)
#include <cuda_runtime.h>
#include <math.h>

// Born-Wolf PSF: params (16,64,2) -> psf (16,64,25,25,25), normalized.
// Kernel A (2 pairs/block): plane[13][35] + norm -> interp-ready float2 pair table.
// Kernel B (2 pairs/block): radial bilinear interp + z-mirror + write, with
// double-buffered pair-table prefetch.

#define NHALF 13
#define NR    35
#define NRP   36
#define NPAD  40        // pair-table row stride (float2 units)
#define NI    101
#define MAXP  1024

typedef unsigned long long ull;

__device__ float2 g_pairs[MAXP][NHALF][NPAD];   // 4.1 MB static scratch

// ---- f32x2 packed helpers (sm_100+) ----
__device__ __forceinline__ ull pack2(float lo, float hi) {
    ull r; asm("mov.b64 %0, {%1,%2};" : "=l"(r) : "f"(lo), "f"(hi)); return r;
}
__device__ __forceinline__ void unpack2(ull v, float& lo, float& hi) {
    asm("mov.b64 {%0,%1}, %2;" : "=f"(lo), "=f"(hi) : "l"(v));
}
__device__ __forceinline__ ull ffma2(ull a, ull b, ull c) {
    ull d; asm("fma.rn.f32x2 %0, %1, %2, %3;" : "=l"(d) : "l"(a), "l"(b), "l"(c)); return d;
}
__device__ __forceinline__ ull fmul2(ull a, ull b) {
    ull d; asm("mul.rn.f32x2 %0, %1, %2;" : "=l"(d) : "l"(a), "l"(b)); return d;
}
__device__ __forceinline__ ull fadd2(ull a, ull b) {
    ull d; asm("add.rn.f32x2 %0, %1, %2;" : "=l"(d) : "l"(a), "l"(b)); return d;
}
#define C2(c) pack2((c), (c))

// Accurate sincos for |x| up to ~1000: Cody-Waite 2-pi reduction + __sincosf.
__device__ __forceinline__ void rsincos(float x, float* s, float* c) {
    float q = rintf(x * 0.15915494309189535f);
    float r = fmaf(q, -6.28125f, x);
    r = fmaf(q, -1.9353071795864769e-3f, r);
    __sincosf(r, s, c);
}

// Scalar J0 (A&S rational approx, matches reference), fast divides.
__device__ __forceinline__ float bessel_j0f(float x) {
    float ax = fabsf(x);
    if (ax <= 8.0f) {
        float y = x * x;
        float num = -184.9052456f;
        num = fmaf(num, y, 77392.33017f);
        num = fmaf(num, y, -11214424.18f);
        num = fmaf(num, y, 651619640.7f);
        num = fmaf(num, y, -13362590354.0f);
        num = fmaf(num, y, 57568490574.0f);
        float den = y + 267.8532712f;
        den = fmaf(den, y, 59272.64853f);
        den = fmaf(den, y, 9494680.718f);
        den = fmaf(den, y, 1029532985.0f);
        den = fmaf(den, y, 57568490411.0f);
        return __fdividef(num, den);
    } else {
        float z = __fdividef(8.0f, ax);
        float y2 = z * z;
        float p1 = 0.2093887211e-6f;
        p1 = fmaf(p1, y2, -0.2073370639e-5f);
        p1 = fmaf(p1, y2, 0.2734510407e-4f);
        p1 = fmaf(p1, y2, -0.1098628627e-2f);
        p1 = fmaf(p1, y2, 1.0f);
        float p2 = -0.934935152e-7f;
        p2 = fmaf(p2, y2, 0.7621095161e-6f);
        p2 = fmaf(p2, y2, -0.6911147651e-5f);
        p2 = fmaf(p2, y2, 0.1430488765e-3f);
        p2 = fmaf(p2, y2, -0.1562499995e-1f);
        float s, c;
        rsincos(ax - 0.785398164f, &s, &c);
        return rsqrtf(ax) * 0.7978845608028654f * (c * p1 - z * s * p2);
    }
}

// Packed J0 for a pair of non-negative args (x0 <= x1).
__device__ __forceinline__ void j0_pair(float x0, float x1, float& r0, float& r1) {
    if (x1 <= 8.0f) {
        ull x = pack2(x0, x1);
        ull y = fmul2(x, x);
        ull num = C2(-184.9052456f);
        num = ffma2(num, y, C2(77392.33017f));
        num = ffma2(num, y, C2(-11214424.18f));
        num = ffma2(num, y, C2(651619640.7f));
        num = ffma2(num, y, C2(-13362590354.0f));
        num = ffma2(num, y, C2(57568490574.0f));
        ull den = fadd2(y, C2(267.8532712f));
        den = ffma2(den, y, C2(59272.64853f));
        den = ffma2(den, y, C2(9494680.718f));
        den = ffma2(den, y, C2(1029532985.0f));
        den = ffma2(den, y, C2(57568490411.0f));
        float n0, n1, d0, d1;
        unpack2(num, n0, n1); unpack2(den, d0, d1);
        r0 = __fdividef(n0, d0);
        r1 = __fdividef(n1, d1);
    } else if (x0 > 8.0f) {
        float z0 = __fdividef(8.0f, x0), z1 = __fdividef(8.0f, x1);
        ull z = pack2(z0, z1);
        ull y2 = fmul2(z, z);
        ull p1 = C2(0.2093887211e-6f);
        p1 = ffma2(p1, y2, C2(-0.2073370639e-5f));
        p1 = ffma2(p1, y2, C2(0.2734510407e-4f));
        p1 = ffma2(p1, y2, C2(-0.1098628627e-2f));
        p1 = ffma2(p1, y2, C2(1.0f));
        ull p2 = C2(-0.934935152e-7f);
        p2 = ffma2(p2, y2, C2(0.7621095161e-6f));
        p2 = ffma2(p2, y2, C2(-0.6911147651e-5f));
        p2 = ffma2(p2, y2, C2(0.1430488765e-3f));
        p2 = ffma2(p2, y2, C2(-0.1562499995e-1f));
        float p1a, p1b, p2a, p2b;
        unpack2(p1, p1a, p1b); unpack2(p2, p2a, p2b);
        float s0, c0, s1, c1;
        rsincos(x0 - 0.785398164f, &s0, &c0);
        rsincos(x1 - 0.785398164f, &s1, &c1);
        r0 = rsqrtf(x0) * 0.7978845608028654f * (c0 * p1a - z0 * s0 * p2a);
        r1 = rsqrtf(x1) * 0.7978845608028654f * (c1 * p1b - z1 * s1 * p2b);
    } else {
        r0 = bessel_j0f(x0);
        r1 = bessel_j0f(x1);
    }
}

// =========================== Kernel A: compute ===========================
__global__ __launch_bounds__(256, 5)
void bw_plane_kernel(const float* __restrict__ params, int npairs) {
    const int tid  = threadIdx.x;
    const int warp = tid >> 5;
    const int lane = tid & 31;

    __shared__ float  sA[NI][NRP];       // transposed J0 table
    __shared__ float2 sCS[NHALF][NI];
    __shared__ float  sPlane[NHALF][NRP];
    __shared__ float  sPart[117][8];     // group-1 matmul partials
    __shared__ float  sCol[NRP];
    __shared__ float  sRed[8];
    __shared__ float  sInv;

    for (int pp = 0; pp < 2; ++pp) {
        const int p = blockIdx.x * 2 + pp;
        if (p >= npairs) break;

        const float lam = fabsf(params[2 * p]);
        const float n   = fabsf(params[2 * p + 1]);
        const float k   = 6.2831853071795864769f / lam;
        const float kn  = k * n;
        const float kz2 = 0.5f * k * n * n;

        // Phase 1: A[i][r] = J0(kn*(r/2)*rho_i) * rho_i * tw_i
        // warp-aligned: warp owns rows r = warp, warp+8, ...; lanes cover rho pairs.
        for (int r = warp; r < NR; r += 8) {
            const float a = kn * (0.5f * (float)r);
            {   // chunk 1: i0 = 2*lane, i1 = i0+1  (i in [0,64))
                int i0 = 2 * lane, i1 = i0 + 1;
                float rho0 = (float)i0 * 0.01f, rho1 = (float)i1 * 0.01f;
                float j0a, j0b;
                j0_pair(a * rho0, a * rho1, j0a, j0b);
                float tw0 = (i0 == 0) ? 0.005f : 0.01f;
                sA[i0][r] = j0a * rho0 * tw0;
                sA[i1][r] = j0b * rho1 * 0.01f;
            }
            if (lane < 19) {  // chunk 2: i0 = 64+2*lane (i in [64,101))
                int i0 = 64 + 2 * lane;
                int i1 = (i0 < NI - 1) ? i0 + 1 : i0;
                float rho0 = (float)i0 * 0.01f, rho1 = (float)i1 * 0.01f;
                float j0a, j0b;
                j0_pair(a * rho0, a * rho1, j0a, j0b);
                float tw0 = (i0 == NI - 1) ? 0.005f : 0.01f;
                sA[i0][r] = j0a * rho0 * tw0;
                if (i1 != i0) sA[i1][r] = j0b * rho1 * 0.01f;
            }
        }
        // Phase 2: CS[z][i] via z-rotor (sign of sin irrelevant: squared later)
        if (tid < NI) {
            float rho = (float)tid * 0.01f;
            float th = kz2 * rho * rho;
            float c1, s1;
            rsincos(th, &s1, &c1);
            sCS[0][tid] = make_float2(1.0f, 0.0f);
            sCS[1][tid] = make_float2(c1, s1);
            float c = c1, s = s1;
            #pragma unroll
            for (int z = 2; z < NHALF; ++z) {
                float cn = fmaf(c, c1, -s * s1);
                float sn = fmaf(s, c1,  c * s1);
                sCS[z][tid] = make_float2(cn, sn);
                c = cn; s = sn;
            }
        }
        __syncthreads();

        // Phase 3: plane[z][r] matmul split over 8 warps (two rho-half groups)
        const int g = tid >> 7;         // 0: i in [0,51), 1: i in [51,101)
        const int t = tid & 127;
        ull re01 = 0, re23 = 0, im01 = 0, im23 = 0;
        int z = 0, r0 = 0;
        if (t < NHALF * 9) {
            z = t / 9;
            int rq = t - z * 9;
            r0 = rq * 4;
            const int ib = g ? 51 : 0;
            const int ie = g ? NI : 51;
            #pragma unroll 5
            for (int i = ib; i < ie; ++i) {
                float4 av = *(const float4*)&sA[i][r0];
                float2 cs = sCS[z][i];
                ull a01 = pack2(av.x, av.y), a23 = pack2(av.z, av.w);
                ull cc = pack2(cs.x, cs.x), ss = pack2(cs.y, cs.y);
                re01 = ffma2(a01, cc, re01);
                re23 = ffma2(a23, cc, re23);
                im01 = ffma2(a01, ss, im01);
                im23 = ffma2(a23, ss, im23);
            }
            if (g == 1) {
                float v0, v1;
                unpack2(re01, v0, v1); sPart[t][0] = v0; sPart[t][1] = v1;
                unpack2(re23, v0, v1); sPart[t][2] = v0; sPart[t][3] = v1;
                unpack2(im01, v0, v1); sPart[t][4] = v0; sPart[t][5] = v1;
                unpack2(im23, v0, v1); sPart[t][6] = v0; sPart[t][7] = v1;
            }
        }
        __syncthreads();
        if (g == 0 && t < NHALF * 9) {
            float pr0, pr1, pr2, pr3, pi0, pi1, pi2, pi3;
            unpack2(re01, pr0, pr1); unpack2(re23, pr2, pr3);
            unpack2(im01, pi0, pi1); unpack2(im23, pi2, pi3);
            pr0 += sPart[t][0]; pr1 += sPart[t][1];
            pr2 += sPart[t][2]; pr3 += sPart[t][3];
            pi0 += sPart[t][4]; pi1 += sPart[t][5];
            pi2 += sPart[t][6]; pi3 += sPart[t][7];
            sPlane[z][r0]     = pr0 * pr0 + pi0 * pi0;
            sPlane[z][r0 + 1] = pr1 * pr1 + pi1 * pi1;
            sPlane[z][r0 + 2] = pr2 * pr2 + pi2 * pi2;
            if (r0 + 3 < NR) sPlane[z][r0 + 3] = pr3 * pr3 + pi3 * pi3;
        }
        __syncthreads();

        // Phase 4: colsum[r] = plane[0][r] + 2*sum_{z>=1} plane[z][r]
        if (tid < NR) {
            float s = sPlane[0][tid];
            #pragma unroll
            for (int zz = 1; zz < NHALF; ++zz) s += 2.0f * sPlane[zz][tid];
            sCol[tid] = s;
        }
        __syncthreads();

        // Phase 5: normalization sum over (y,x)
        float part = 0.0f;
        for (int pix = tid; pix < 625; pix += 256) {
            int yy = pix / 25, xx = pix - yy * 25;
            float dx = (float)(xx - 12), dy = (float)(yy - 12);
            float rp = sqrtf(dx * dx + dy * dy);
            int i1 = (int)floorf(rp * 2.0f);
            float d1 = (rp - 0.5f * (float)i1) * 2.0f;
            part += d1 * sCol[i1 + 1] + (1.0f - d1) * sCol[i1];
        }
        #pragma unroll
        for (int o = 16; o; o >>= 1) part += __shfl_down_sync(0xFFFFFFFFu, part, o);
        if (lane == 0) sRed[warp] = part;
        __syncthreads();
        if (tid == 0) {
            float tt = 0.0f;
            #pragma unroll
            for (int w = 0; w < 8; ++w) tt += sRed[w];
            sInv = 1.0f / tt;
        }
        __syncthreads();
        const float inv = sInv;

        // Phase 6: write interp-ready pair table
        for (int idx = tid; idx < NHALF * NPAD; idx += 256) {
            int zz = idx / NPAD, r = idx - zz * NPAD;
            float lo = (r < NR)     ? sPlane[zz][r]     * inv : 0.0f;
            float hi = (r + 1 < NR) ? sPlane[zz][r + 1] * inv : 0.0f;
            g_pairs[p][zz][r] = make_float2(lo, hi);
        }
        __syncthreads();   // smem reuse for next pair
    }
}

// =========================== Kernel B: writer ===========================
__global__ __launch_bounds__(640, 3)
void bw_write_kernel(float* __restrict__ out, int npairs) {
    const int tid = threadIdx.x;
    const int p0 = blockIdx.x * 2;
    const int cnt = min(2, npairs - p0);
    if (cnt <= 0) return;

    __shared__ float2 sPair[2][NHALF * NPAD];   // double-buffered, 8.3 KB

    // per-pixel constants (pair-invariant)
    int i1 = 0; float d1 = 0.f, d2 = 0.f;
    if (tid < 625) {
        int yy = tid / 25, xx = tid - yy * 25;
        float dx = (float)(xx - 12), dy = (float)(yy - 12);
        float rp = sqrtf(dx * dx + dy * dy);
        i1 = (int)floorf(rp * 2.0f);
        d1 = (rp - 0.5f * (float)i1) * 2.0f;
        d2 = 1.0f - d1;
    }

    const bool pf = (tid < NHALF * NPAD);
    if (pf) sPair[0][tid] = g_pairs[p0][0][tid];
    __syncthreads();

    for (int pp = 0; pp < cnt; ++pp) {
        const int cur = pp & 1;
        float2 nxt;
        const bool havenext = (pp + 1 < cnt);
        if (havenext && pf) nxt = g_pairs[p0 + pp + 1][0][tid];  // prefetch (LDG in flight)

        if (tid < 625) {
            float v[NHALF];
            #pragma unroll
            for (int zo = 0; zo < NHALF; ++zo) {
                float2 pr = sPair[cur][zo * NPAD + i1];   // LDS.64
                v[zo] = fmaf(d1, pr.y, d2 * pr.x);
            }
            float* po = out + (size_t)(p0 + pp) * 15625 + tid;
            #pragma unroll
            for (int z = 0; z < 25; ++z) {
                int zo = (z < 12) ? (12 - z) : (z - 12);
                po[z * 625] = v[zo];
            }
        }
        if (havenext && pf) sPair[1 - cur][tid] = nxt;
        __syncthreads();
    }
}

extern "C" void kernel_launch(void* const* d_in, const int* in_sizes, int n_in,
                              void* d_out, int out_size) {
    const float* params = (const float*)d_in[0];
    float* out = (float*)d_out;
    int npairs = in_sizes[0] / 2;   // 16*64 = 1024
    int nblkA = (npairs + 1) / 2;
    int nblkB = (npairs + 1) / 2;
    bw_plane_kernel<<<nblkA, 256>>>(params, npairs);
    bw_write_kernel<<<nblkB, 640>>>(out, npairs);
}

// round 5
// speedup vs baseline: 1.4677x; 1.4677x over previous
#include <cuda_runtime.h>
#include <math.h>

// Born-Wolf PSF: params (16,64,2) -> psf (16,64,25,25,25), normalized.
// Fused single kernel, one (b,c) pair per block.
//   phase1: A[i][r] = J0(kn*(r/2)*rho_i)*rho_i*tw_i   (101 x 35, f32x2-packed J0)
//   phase3: plane[z][r] = |sum_i A * e^{-i w}|^2 via f32x2 matmul with in-loop
//           double-rotor cos/sin (w = base*i^2), rho-range split over 234 threads
//   phase4: colsum dot constexpr W[] -> norm; raw pair table for interp
//   phase6: radial bilinear interp from constexpr pixel table + z-mirror + write

#define NHALF 13
#define NR    35
#define NRP   36
#define NI    101

typedef unsigned long long ull;

// ---------------- compile-time geometry tables ----------------
constexpr double csqrt_(double x) {
    double g = x > 1.0 ? x : 1.0;
    for (int i = 0; i < 64; ++i) g = 0.5 * (g + x / g);
    return g;
}
struct alignas(16) PixEntry { float d1, d2; int i1, pad; };
struct Tabs {
    PixEntry pix[625];
    float W[40];
    constexpr Tabs() : pix(), W() {
        double Wd[40] = {};
        for (int yy = 0; yy < 25; ++yy)
            for (int xx = 0; xx < 25; ++xx) {
                double dx = xx - 12, dy = yy - 12;
                double rp = csqrt_(dx * dx + dy * dy);
                double t2 = 2.0 * rp;
                int i1 = (int)t2;
                double d1 = t2 - (double)i1;
                int q = yy * 25 + xx;
                pix[q].d1 = (float)d1;
                pix[q].d2 = (float)(1.0 - d1);
                pix[q].i1 = i1;
                pix[q].pad = 0;
                Wd[i1]     += 1.0 - d1;
                Wd[i1 + 1] += d1;
            }
        for (int i = 0; i < 40; ++i) W[i] = (float)Wd[i];
    }
};
__device__ constexpr Tabs g_tabs{};

// ---------------- f32x2 packed helpers (sm_100+) ----------------
__device__ __forceinline__ ull pack2(float lo, float hi) {
    ull r; asm("mov.b64 %0, {%1,%2};" : "=l"(r) : "f"(lo), "f"(hi)); return r;
}
__device__ __forceinline__ void unpack2(ull v, float& lo, float& hi) {
    asm("mov.b64 {%0,%1}, %2;" : "=f"(lo), "=f"(hi) : "l"(v));
}
__device__ __forceinline__ ull ffma2(ull a, ull b, ull c) {
    ull d; asm("fma.rn.f32x2 %0, %1, %2, %3;" : "=l"(d) : "l"(a), "l"(b), "l"(c)); return d;
}
__device__ __forceinline__ ull fmul2(ull a, ull b) {
    ull d; asm("mul.rn.f32x2 %0, %1, %2;" : "=l"(d) : "l"(a), "l"(b)); return d;
}
__device__ __forceinline__ ull fadd2(ull a, ull b) {
    ull d; asm("add.rn.f32x2 %0, %1, %2;" : "=l"(d) : "l"(a), "l"(b)); return d;
}
#define C2(c) pack2((c), (c))

// Accurate sincos for |x| up to ~1000: Cody-Waite 2-pi reduction + __sincosf.
__device__ __forceinline__ void rsincos(float x, float* s, float* c) {
    float q = rintf(x * 0.15915494309189535f);
    float r = fmaf(q, -6.28125f, x);
    r = fmaf(q, -1.9353071795864769e-3f, r);
    __sincosf(r, s, c);
}

// Scalar J0 (A&S rational approx, matches reference), fast divides.
__device__ __forceinline__ float bessel_j0f(float x) {
    float ax = fabsf(x);
    if (ax <= 8.0f) {
        float y = x * x;
        float num = -184.9052456f;
        num = fmaf(num, y, 77392.33017f);
        num = fmaf(num, y, -11214424.18f);
        num = fmaf(num, y, 651619640.7f);
        num = fmaf(num, y, -13362590354.0f);
        num = fmaf(num, y, 57568490574.0f);
        float den = y + 267.8532712f;
        den = fmaf(den, y, 59272.64853f);
        den = fmaf(den, y, 9494680.718f);
        den = fmaf(den, y, 1029532985.0f);
        den = fmaf(den, y, 57568490411.0f);
        return __fdividef(num, den);
    } else {
        float z = __fdividef(8.0f, ax);
        float y2 = z * z;
        float p1 = 0.2093887211e-6f;
        p1 = fmaf(p1, y2, -0.2073370639e-5f);
        p1 = fmaf(p1, y2, 0.2734510407e-4f);
        p1 = fmaf(p1, y2, -0.1098628627e-2f);
        p1 = fmaf(p1, y2, 1.0f);
        float p2 = -0.934935152e-7f;
        p2 = fmaf(p2, y2, 0.7621095161e-6f);
        p2 = fmaf(p2, y2, -0.6911147651e-5f);
        p2 = fmaf(p2, y2, 0.1430488765e-3f);
        p2 = fmaf(p2, y2, -0.1562499995e-1f);
        float s, c;
        rsincos(ax - 0.785398164f, &s, &c);
        return rsqrtf(ax) * 0.7978845608028654f * (c * p1 - z * s * p2);
    }
}

// Packed J0 for a pair of non-negative args (x0 <= x1).
__device__ __forceinline__ void j0_pair(float x0, float x1, float& r0, float& r1) {
    if (x1 <= 8.0f) {
        ull x = pack2(x0, x1);
        ull y = fmul2(x, x);
        ull num = C2(-184.9052456f);
        num = ffma2(num, y, C2(77392.33017f));
        num = ffma2(num, y, C2(-11214424.18f));
        num = ffma2(num, y, C2(651619640.7f));
        num = ffma2(num, y, C2(-13362590354.0f));
        num = ffma2(num, y, C2(57568490574.0f));
        ull den = fadd2(y, C2(267.8532712f));
        den = ffma2(den, y, C2(59272.64853f));
        den = ffma2(den, y, C2(9494680.718f));
        den = ffma2(den, y, C2(1029532985.0f));
        den = ffma2(den, y, C2(57568490411.0f));
        float n0, n1, d0, d1;
        unpack2(num, n0, n1); unpack2(den, d0, d1);
        r0 = __fdividef(n0, d0);
        r1 = __fdividef(n1, d1);
    } else if (x0 > 8.0f) {
        float z0 = __fdividef(8.0f, x0), z1 = __fdividef(8.0f, x1);
        ull z = pack2(z0, z1);
        ull y2 = fmul2(z, z);
        ull p1 = C2(0.2093887211e-6f);
        p1 = ffma2(p1, y2, C2(-0.2073370639e-5f));
        p1 = ffma2(p1, y2, C2(0.2734510407e-4f));
        p1 = ffma2(p1, y2, C2(-0.1098628627e-2f));
        p1 = ffma2(p1, y2, C2(1.0f));
        ull p2 = C2(-0.934935152e-7f);
        p2 = ffma2(p2, y2, C2(0.7621095161e-6f));
        p2 = ffma2(p2, y2, C2(-0.6911147651e-5f));
        p2 = ffma2(p2, y2, C2(0.1430488765e-3f));
        p2 = ffma2(p2, y2, C2(-0.1562499995e-1f));
        float p1a, p1b, p2a, p2b;
        unpack2(p1, p1a, p1b); unpack2(p2, p2a, p2b);
        float s0, c0, s1, c1;
        rsincos(x0 - 0.785398164f, &s0, &c0);
        rsincos(x1 - 0.785398164f, &s1, &c1);
        r0 = rsqrtf(x0) * 0.7978845608028654f * (c0 * p1a - z0 * s0 * p2a);
        r1 = rsqrtf(x1) * 0.7978845608028654f * (c1 * p1b - z1 * s1 * p2b);
    } else {
        r0 = bessel_j0f(x0);
        r1 = bessel_j0f(x1);
    }
}

__global__ __launch_bounds__(256, 6)
void bw_psf_kernel(const float* __restrict__ params, float* __restrict__ out) {
    const int p = blockIdx.x;
    const int tid = threadIdx.x;
    const int lane = tid & 31;

    __shared__ float  sA[NI][NRP];        // 14.5 KB
    __shared__ float  sPlane[NHALF][NRP]; // 1.9 KB
    __shared__ float2 sPair[NHALF][40];   // 4.2 KB
    __shared__ float  sPart[117][8];      // 3.7 KB
    __shared__ float  sWcol[40];

    const float lam = fabsf(params[2 * p]);
    const float n   = fabsf(params[2 * p + 1]);
    const float k   = 6.2831853071795864769f / lam;
    const float kn  = k * n;
    const float kz2 = 0.5f * k * n * n;

    // ---- Phase 1: A[i][r] = J0(kn*(r/2)*rho_i) * rho_i * tw_i (pairs of i) ----
    for (int job = tid; job < NR * 51; job += 256) {
        int r = job / 51, ii = job - r * 51;
        int i0 = 2 * ii;
        int i1 = (i0 < NI - 1) ? i0 + 1 : NI - 1;
        float rr = kn * (0.5f * (float)r);
        float rho0 = (float)i0 * 0.01f, rho1 = (float)i1 * 0.01f;
        float j0a, j0b;
        j0_pair(rr * rho0, rr * rho1, j0a, j0b);
        float tw0 = (i0 == 0 || i0 == NI - 1) ? 0.005f : 0.01f;
        float tw1 = (i1 == NI - 1) ? 0.005f : 0.01f;
        sA[i0][r] = j0a * rho0 * tw0;
        if (i1 != i0) sA[i1][r] = j0b * rho1 * tw1;
    }
    __syncthreads();

    // ---- Phase 3: plane matmul, 234 threads, in-loop double-rotor cos/sin ----
    // w(z,i) = base*i^2, base = kz2*z*drho^2. Angle steps: th_i = base*(2i+1),
    // which itself advances by phi = 2*base -> nested rotors (8 FMA/iter).
    const int g = tid >> 7;          // 0: i in [0,51), 1: i in [51,101)
    const int t = tid & 127;
    ull re01 = 0, re23 = 0, im01 = 0, im23 = 0;
    int z = 0, r0 = 0;
    if (t < NHALF * 9) {
        z = t / 9;
        r0 = (t - z * 9) * 4;
        const float base = kz2 * 1e-4f * (float)z;
        float c, s, cd, sd, cphi, sphi;
        {
            float cb, sb;
            rsincos(base, &sb, &cb);
            cphi = fmaf(-2.0f * sb, sb, 1.0f);       // cos(2*base)
            sphi = 2.0f * sb * cb;                    // sin(2*base)
            if (g == 0) {
                c = 1.0f; s = 0.0f;
                cd = cb; sd = sb;                     // th_0 = base
            } else {
                rsincos(base * 2601.0f, &s, &c);      // w at i=51
                rsincos(base * 103.0f, &sd, &cd);     // th_51 = base*103
            }
        }
        const int ib = g ? 51 : 0;
        const int ie = g ? NI : 51;
        #pragma unroll 3
        for (int i = ib; i < ie; ++i) {
            float4 av = *(const float4*)&sA[i][r0];
            ull a01 = pack2(av.x, av.y), a23 = pack2(av.z, av.w);
            ull cc = pack2(c, c), ss = pack2(s, s);
            re01 = ffma2(a01, cc, re01);
            re23 = ffma2(a23, cc, re23);
            im01 = ffma2(a01, ss, im01);
            im23 = ffma2(a23, ss, im23);
            float cn = fmaf(c, cd, -(s * sd));
            float sn = fmaf(s, cd,  (c * sd));
            c = cn; s = sn;
            float cdn = fmaf(cd, cphi, -(sd * sphi));
            float sdn = fmaf(sd, cphi,  (cd * sphi));
            cd = cdn; sd = sdn;
        }
        if (g == 1) {
            float v0, v1;
            unpack2(re01, v0, v1); sPart[t][0] = v0; sPart[t][1] = v1;
            unpack2(re23, v0, v1); sPart[t][2] = v0; sPart[t][3] = v1;
            unpack2(im01, v0, v1); sPart[t][4] = v0; sPart[t][5] = v1;
            unpack2(im23, v0, v1); sPart[t][6] = v0; sPart[t][7] = v1;
        }
    }
    __syncthreads();
    if (g == 0 && t < NHALF * 9) {
        float pr0, pr1, pr2, pr3, pi0, pi1, pi2, pi3;
        unpack2(re01, pr0, pr1); unpack2(re23, pr2, pr3);
        unpack2(im01, pi0, pi1); unpack2(im23, pi2, pi3);
        pr0 += sPart[t][0]; pr1 += sPart[t][1];
        pr2 += sPart[t][2]; pr3 += sPart[t][3];
        pi0 += sPart[t][4]; pi1 += sPart[t][5];
        pi2 += sPart[t][6]; pi3 += sPart[t][7];
        sPlane[z][r0]     = pr0 * pr0 + pi0 * pi0;
        sPlane[z][r0 + 1] = pr1 * pr1 + pi1 * pi1;
        sPlane[z][r0 + 2] = pr2 * pr2 + pi2 * pi2;
        if (r0 + 3 < NR) sPlane[z][r0 + 3] = pr3 * pr3 + pi3 * pi3;
    }
    __syncthreads();

    // ---- Phase 4: colsum dot W (norm prep) + raw pair table ----
    if (tid < NR) {
        float s = sPlane[0][tid];
        #pragma unroll
        for (int zz = 1; zz < NHALF; ++zz) s += 2.0f * sPlane[zz][tid];
        sWcol[tid] = s * g_tabs.W[tid];
    }
    for (int idx = tid; idx < NHALF * NR; idx += 256) {
        int zz = idx / NR, r = idx - zz * NR;
        float lo = sPlane[zz][r];
        float hi = (r < NR - 1) ? sPlane[zz][r + 1] : 0.0f;
        sPair[zz][r] = make_float2(lo, hi);
    }
    __syncthreads();

    // ---- redundant per-warp reduction of sWcol -> inv (no extra barrier) ----
    float v = (lane < NR) ? sWcol[lane] : 0.0f;
    if (lane < 3) v += sWcol[32 + lane];
    #pragma unroll
    for (int o = 16; o; o >>= 1) v += __shfl_xor_sync(0xFFFFFFFFu, v, o);
    const float inv = __fdividef(1.0f, v);

    // ---- Phase 6: interp from constexpr pixel table + z-mirror + write ----
    const float4* ptab = reinterpret_cast<const float4*>(g_tabs.pix);
    for (int pix = tid; pix < 625; pix += 256) {
        float4 e = ptab[pix];                 // {d1, d2, i1 bits, pad}
        int i1 = __float_as_int(e.z);
        float d1 = e.x * inv, d2 = e.y * inv;
        float vv[NHALF];
        #pragma unroll
        for (int zo = 0; zo < NHALF; ++zo) {
            float2 pr = sPair[zo][i1];        // LDS.64
            vv[zo] = fmaf(d1, pr.y, d2 * pr.x);
        }
        float* po = out + (size_t)p * 15625 + pix;
        #pragma unroll
        for (int zz = 0; zz < 25; ++zz) {
            int zo = (zz < 12) ? (12 - zz) : (zz - 12);
            po[zz * 625] = vv[zo];
        }
    }
}

extern "C" void kernel_launch(void* const* d_in, const int* in_sizes, int n_in,
                              void* d_out, int out_size) {
    const float* params = (const float*)d_in[0];
    float* out = (float*)d_out;
    int npairs = in_sizes[0] / 2;   // 16*64 = 1024
    bw_psf_kernel<<<npairs, 256>>>(params, out);
}